// round 3
// baseline (speedup 1.0000x reference)
#include <cuda_runtime.h>
#include <cuda_bf16.h>
#include <math.h>
#include <float.h>

// ---------------- problem constants (fixed dataset) ----------------
#define NPTS    20000
#define PD      64          // point feature dim
#define GD      256         // grid feature dim
#define HH      96
#define WW      96
#define G       (HH*WW)     // 9216 grid points
#define KNN     32
#define HID     64
#define NC      64          // bin grid 64x64
#define NCELLS  (NC*NC)
#define CAP     1024        // candidate capacity per grid point
#define EPSLN   1e-5f

// step = f32(1/95), exactly as JAX f32 linspace computes it
#define STEP    (1.0f/95.0f)

// ---------------- scratch (device globals, no allocations) ----------------
__device__ float  g_pf[NPTS*GD];       // projected point features (20.5 MB)
__device__ int    g_cnt[NCELLS];
__device__ int    g_start[NCELLS+1];
__device__ int    g_cur[NCELLS];
__device__ float4 g_pts[NPTS];         // (px, py, p2, idx-as-float), binned order
__device__ int    g_knn[G*KNN];
__device__ float  g_mid[G*GD];         // aggregated features before out-proj

// exact-rounding helpers for the KNN distance path (must bit-match reference)
__device__ __forceinline__ float grid_coord(int i) {
    // JAX f32 linspace: round(i * round(1/95))
    return __fmul_rn((float)i, STEP);
}
__device__ __forceinline__ float sum_sq(float x, float y) {
    // jnp.sum(v*v): elementwise multiply then add, NO fma
    return __fadd_rn(__fmul_rn(x, x), __fmul_rn(y, y));
}
__device__ __forceinline__ float dot_ref(float gx, float gy, float px, float py) {
    // XLA rewrites K=2 dot -> multiply + reduce, no contraction:
    // round both products, then add. NO FMA.
    return __fadd_rn(__fmul_rn(gx, px), __fmul_rn(gy, py));
}
__device__ __forceinline__ float dist2_ref(float g2, float m, float p2) {
    // (g2 - 2*m) + p2, left-to-right; 2*m is exact
    return __fadd_rn(__fsub_rn(g2, __fmul_rn(2.0f, m)), p2);
}

// ======================================================================
// Kernel 1: pf = point_features @ W_feat^T + b_feat   [20000 x 256]
// 16 rows per block, 256 threads (one output column per thread).
// ======================================================================
__global__ __launch_bounds__(256) void pf_kernel(
    const float* __restrict__ feat,   // [NPTS,64]
    const float* __restrict__ Wf,     // [256,64]
    const float* __restrict__ bf)     // [256]
{
    __shared__ float sW[32*257];      // transposed W tile [kk][c], padded
    __shared__ float sF[16*32];       // feature tile [r][kk]
    const int t    = threadIdx.x;
    const int row0 = blockIdx.x * 16;

    float acc[16];
#pragma unroll
    for (int r = 0; r < 16; r++) acc[r] = 0.0f;

    for (int kt = 0; kt < PD; kt += 32) {
#pragma unroll
        for (int i = 0; i < 32; i++) {
            int e  = i * 256 + t;
            int kk = e & 31;
            int c  = e >> 5;
            sW[kk*257 + c] = Wf[c*PD + kt + kk];
        }
#pragma unroll
        for (int i = 0; i < 2; i++) {
            int e = i * 256 + t;     // 512 elems
            int r = e >> 5, kk = e & 31;
            sF[r*32 + kk] = feat[(row0 + r)*PD + kt + kk];
        }
        __syncthreads();
#pragma unroll
        for (int kk = 0; kk < 32; kk++) {
            float w = sW[kk*257 + t];
#pragma unroll
            for (int r = 0; r < 16; r++)
                acc[r] = fmaf(sF[r*32 + kk], w, acc[r]);
        }
        __syncthreads();
    }
    float b = bf[t];
#pragma unroll
    for (int r = 0; r < 16; r++)
        g_pf[(size_t)(row0 + r)*GD + t] = acc[r] + b;
}

// ======================================================================
// Binning kernels
// ======================================================================
__device__ __forceinline__ int cell_of(float px, float py) {
    int cx = (int)(px * NC); cx = min(max(cx, 0), NC-1);
    int cy = (int)(py * NC); cy = min(max(cy, 0), NC-1);
    return cy * NC + cx;
}

__global__ void zero_cnt_kernel() {
    int i = blockIdx.x * blockDim.x + threadIdx.x;
    if (i < NCELLS) g_cnt[i] = 0;
}

__global__ void bin_count_kernel(const float* __restrict__ pc) {
    int n = blockIdx.x * blockDim.x + threadIdx.x;
    if (n >= NPTS) return;
    atomicAdd(&g_cnt[cell_of(pc[2*n], pc[2*n+1])], 1);
}

__global__ __launch_bounds__(1024) void bin_scan_kernel() {
    __shared__ int wsum[32];
    int t = threadIdx.x;          // 1024 threads, 4 cells each
    int v[4], s = 0;
#pragma unroll
    for (int i = 0; i < 4; i++) { v[i] = g_cnt[t*4 + i]; s += v[i]; }
    int lane = t & 31, wid = t >> 5;
    int incl = s;
#pragma unroll
    for (int o = 1; o < 32; o <<= 1) {
        int u = __shfl_up_sync(0xffffffffu, incl, o);
        if (lane >= o) incl += u;
    }
    if (lane == 31) wsum[wid] = incl;
    __syncthreads();
    if (wid == 0) {
        int ws = wsum[lane];
#pragma unroll
        for (int o = 1; o < 32; o <<= 1) {
            int u = __shfl_up_sync(0xffffffffu, ws, o);
            if (lane >= o) ws += u;
        }
        wsum[lane] = ws;
    }
    __syncthreads();
    int base = (wid > 0 ? wsum[wid-1] : 0) + incl - s;  // exclusive prefix
    int run = base;
#pragma unroll
    for (int i = 0; i < 4; i++) {
        g_start[t*4 + i] = run;
        g_cur[t*4 + i]   = run;
        run += v[i];
    }
    if (t == 1023) g_start[NCELLS] = run;
}

__global__ void bin_scatter_kernel(const float* __restrict__ pc) {
    int n = blockIdx.x * blockDim.x + threadIdx.x;
    if (n >= NPTS) return;
    float px = pc[2*n], py = pc[2*n+1];
    int pos = atomicAdd(&g_cur[cell_of(px, py)], 1);
    // p2 must match jnp.sum(p*p, -1): multiply then add, no fma
    g_pts[pos] = make_float4(px, py, sum_sq(px, py), __int_as_float(n));
}

// ======================================================================
// Kernel: exact KNN (K=32) per grid point via adaptive-radius candidates
// One block (128 threads) per grid point. Bitonic sort by (dist2, idx).
// dist2 arithmetic replicates the reference bit-for-bit.
// ======================================================================
__global__ __launch_bounds__(128) void knn_kernel()
{
    __shared__ float s_d[CAP];
    __shared__ int   s_i[CAP];
    __shared__ int   s_cnt;

    const int g   = blockIdx.x;
    const int tid = threadIdx.x;
    const int wx = g % WW, hy = g / WW;
    const float gx = grid_coord(wx), gy = grid_coord(hy);
    const float g2 = sum_sq(gx, gy);

    float R2 = 0.0015f;
    int cnt = 0;
    for (int iter = 0; iter < 24; iter++) {
        if (tid == 0) s_cnt = 0;
        __syncthreads();
        float R = sqrtf(R2);
        int cx0 = max(0,    (int)floorf((gx - R) * NC));
        int cx1 = min(NC-1, (int)floorf((gx + R) * NC));
        int cy0 = max(0,    (int)floorf((gy - R) * NC));
        int cy1 = min(NC-1, (int)floorf((gy + R) * NC));
        for (int cy = cy0; cy <= cy1; cy++) {
            int b = g_start[cy*NC + cx0];
            int e = g_start[cy*NC + cx1 + 1];
            for (int j = b + tid; j < e; j += 128) {
                float4 p = g_pts[j];
                float m = dot_ref(gx, gy, p.x, p.y);
                float d = dist2_ref(g2, m, p.z);
                if (d <= R2) {
                    int pos = atomicAdd(&s_cnt, 1);
                    if (pos < CAP) { s_d[pos] = d; s_i[pos] = __float_as_int(p.w); }
                }
            }
        }
        __syncthreads();
        cnt = s_cnt;
        if (cnt >= KNN && cnt <= CAP) break;
        R2 = (cnt < KNN) ? R2 * 2.0f : R2 * 0.5f;
        __syncthreads();
    }

    // pad to power of two
    int M = KNN;
    while (M < cnt) M <<= 1;
    for (int j = cnt + tid; j < M; j += 128) { s_d[j] = FLT_MAX; s_i[j] = 0x7fffffff; }
    __syncthreads();

    // bitonic sort ascending by (d, idx)
    for (int len = 2; len <= M; len <<= 1) {
        for (int stride = len >> 1; stride > 0; stride >>= 1) {
            for (int j = tid; j < (M >> 1); j += 128) {
                int i  = 2*j - (j & (stride - 1));
                int ip = i + stride;
                float d1 = s_d[i], d2 = s_d[ip];
                int   i1 = s_i[i], i2 = s_i[ip];
                bool up = ((i & len) == 0);
                bool gt = (d1 > d2) || (d1 == d2 && i1 > i2);
                bool lt = (d1 < d2) || (d1 == d2 && i1 < i2);
                if (up ? gt : lt) {
                    s_d[i] = d2; s_d[ip] = d1;
                    s_i[i] = i2; s_i[ip] = i1;
                }
            }
            __syncthreads();
        }
    }
    if (tid < KNN) g_knn[g*KNN + tid] = s_i[tid];
}

// ======================================================================
// Kernel: attention MLP + softmax + weighted feature gather
// One block (256 threads) per grid point.
// ======================================================================
__global__ __launch_bounds__(256) void attn_gather_kernel(
    const float* __restrict__ pc,
    const float* __restrict__ W1, const float* __restrict__ b1,
    const float* __restrict__ W2, const float* __restrict__ b2)
{
    __shared__ int   sk[KNN];
    __shared__ float sdx[KNN], sdy[KNN], sdd[KNN];
    __shared__ float slog[KNN], swt[KNN];
    __shared__ float sW1[HID*3], sb1[HID], sW2[HID];

    const int g = blockIdx.x;
    const int t = threadIdx.x;
    const int wx = g % WW, hy = g / WW;
    const float gx = grid_coord(wx), gy = grid_coord(hy);

    if (t < HID) { sb1[t] = b1[t]; sW2[t] = W2[t]; }
    if (t < HID*3) sW1[t] = W1[t];
    if (t < KNN) {
        int id = g_knn[g*KNN + t];
        sk[t] = id;
        float px = pc[2*id], py = pc[2*id+1];
        float dx = __fsub_rn(gx, px), dy = __fsub_rn(gy, py);
        sdx[t] = dx; sdy[t] = dy;
        sdd[t] = sqrtf(sum_sq(dx, dy));
    }
    __syncthreads();

    // MLP: thread t handles neighbor k = t/8, hidden slice of 8
    {
        int k  = t >> 3;
        int j0 = (t & 7) * 8;
        float dx = sdx[k], dy = sdy[k], dd = sdd[k];
        float acc = 0.0f;
#pragma unroll
        for (int jj = 0; jj < 8; jj++) {
            int j = j0 + jj;
            float pre = sW1[j*3]*dx + sW1[j*3+1]*dy + sW1[j*3+2]*dd + sb1[j];
            float ge  = 0.5f * pre * (1.0f + erff(pre * 0.70710678118654752f));
            acc += sW2[j] * ge;
        }
#pragma unroll
        for (int o = 4; o >= 1; o >>= 1)
            acc += __shfl_down_sync(0xffffffffu, acc, o, 8);
        if ((t & 7) == 0) slog[k] = acc + b2[0];
    }
    __syncthreads();

    // softmax over 32 neighbors (warp 0)
    if (t < 32) {
        float l = slog[t];
        float m = l;
#pragma unroll
        for (int o = 16; o >= 1; o >>= 1) m = fmaxf(m, __shfl_xor_sync(0xffffffffu, m, o));
        float e = expf(l - m);
        float s = e;
#pragma unroll
        for (int o = 16; o >= 1; o >>= 1) s += __shfl_xor_sync(0xffffffffu, s, o);
        swt[t] = e / s;
    }
    __syncthreads();

    // weighted gather: column c = t
    float acc = 0.0f;
#pragma unroll 8
    for (int k = 0; k < KNN; k++)
        acc = fmaf(swt[k], g_pf[(size_t)sk[k]*GD + t], acc);
    g_mid[(size_t)g*GD + t] = acc;
}

// ======================================================================
// Kernel: out = mid @ W_out^T + b_out, then LayerNorm. 32 rows/block.
// Dynamic smem: Wt[64][257] + In[32][64] + Out[32][257]
// ======================================================================
__global__ __launch_bounds__(256) void outproj_ln_kernel(
    const float* __restrict__ Wo,   // [256,256]
    const float* __restrict__ bo,
    const float* __restrict__ lng,
    const float* __restrict__ lnb,
    float* __restrict__ out)
{
    extern __shared__ float sm[];
    float* sW  = sm;                    // 64*257
    float* sIn = sm + 64*257;           // 32*64
    float* sOut= sIn + 32*64;           // 32*257
    __shared__ float sMu[32], sRs[32];

    const int t    = threadIdx.x;
    const int row0 = blockIdx.x * 32;

    float acc[32];
#pragma unroll
    for (int r = 0; r < 32; r++) acc[r] = 0.0f;

    for (int kt = 0; kt < GD; kt += 64) {
#pragma unroll
        for (int i = 0; i < 64; i++) {
            int e  = i * 256 + t;
            int kk = e & 63;
            int c  = e >> 6;
            sW[kk*257 + c] = Wo[c*GD + kt + kk];
        }
#pragma unroll
        for (int i = 0; i < 8; i++) {
            int e = i * 256 + t;   // 2048 elems
            int r = e >> 6, kk = e & 63;
            sIn[r*64 + kk] = g_mid[(size_t)(row0 + r)*GD + kt + kk];
        }
        __syncthreads();
#pragma unroll
        for (int kk = 0; kk < 64; kk++) {
            float w = sW[kk*257 + t];
#pragma unroll
            for (int r = 0; r < 32; r++)
                acc[r] = fmaf(sIn[r*64 + kk], w, acc[r]);
        }
        __syncthreads();
    }

    float bb = bo[t];
#pragma unroll
    for (int r = 0; r < 32; r++) sOut[r*257 + t] = acc[r] + bb;
    __syncthreads();

    // per-row mean/var (8 warps x 4 rows)
    const int lane = t & 31, wid = t >> 5;
    for (int r = wid; r < 32; r += 8) {
        float s = 0.0f;
#pragma unroll
        for (int i = lane; i < GD; i += 32) s += sOut[r*257 + i];
#pragma unroll
        for (int o = 16; o >= 1; o >>= 1) s += __shfl_xor_sync(0xffffffffu, s, o);
        float mu = s * (1.0f / GD);
        float v = 0.0f;
#pragma unroll
        for (int i = lane; i < GD; i += 32) {
            float d = sOut[r*257 + i] - mu;
            v = fmaf(d, d, v);
        }
#pragma unroll
        for (int o = 16; o >= 1; o >>= 1) v += __shfl_xor_sync(0xffffffffu, v, o);
        if (lane == 0) { sMu[r] = mu; sRs[r] = rsqrtf(v * (1.0f / GD) + EPSLN); }
    }
    __syncthreads();

    float gsc = lng[t], bsc = lnb[t];
#pragma unroll
    for (int r = 0; r < 32; r++) {
        float val = (sOut[r*257 + t] - sMu[r]) * sRs[r] * gsc + bsc;
        out[(size_t)(row0 + r)*GD + t] = val;
    }
}

// ======================================================================
// launcher
// ======================================================================
extern "C" void kernel_launch(void* const* d_in, const int* in_sizes, int n_in,
                              void* d_out, int out_size)
{
    const float* point_features = (const float*)d_in[0];
    const float* point_coords   = (const float*)d_in[1];
    const float* W_feat         = (const float*)d_in[2];
    const float* b_feat         = (const float*)d_in[3];
    const float* W1             = (const float*)d_in[4];
    const float* b1             = (const float*)d_in[5];
    const float* W2             = (const float*)d_in[6];
    const float* b2             = (const float*)d_in[7];
    const float* W_out          = (const float*)d_in[8];
    const float* b_out          = (const float*)d_in[9];
    const float* ln_g           = (const float*)d_in[10];
    const float* ln_b           = (const float*)d_in[11];
    float* out = (float*)d_out;

    const int SMEM8 = (64*257 + 32*64 + 32*257) * (int)sizeof(float);
    cudaFuncSetAttribute(outproj_ln_kernel,
                         cudaFuncAttributeMaxDynamicSharedMemorySize, SMEM8);

    // 1. feature projection
    pf_kernel<<<NPTS/16, 256>>>(point_features, W_feat, b_feat);

    // 2. binning
    zero_cnt_kernel<<<(NCELLS+255)/256, 256>>>();
    bin_count_kernel<<<(NPTS+255)/256, 256>>>(point_coords);
    bin_scan_kernel<<<1, 1024>>>();
    bin_scatter_kernel<<<(NPTS+255)/256, 256>>>(point_coords);

    // 3. exact KNN
    knn_kernel<<<G, 128>>>();

    // 4. attention + gather
    attn_gather_kernel<<<G, 256>>>(point_coords, W1, b1, W2, b2);

    // 5. output projection + layernorm
    outproj_ln_kernel<<<G/32, 256, SMEM8>>>(W_out, b_out, ln_g, ln_b, out);
}